// round 13
// baseline (speedup 1.0000x reference)
#include <cuda_runtime.h>
#include <float.h>

#define L_SEQ 4096
#define N_TOTAL 512
#define WPB 8            // warps per block
#define TPB (WPB * 32)
#define SX_WORDS 8192    // P + L <= 4094 + 4096 = 8190 <= 8192 floats = 32KB
#define MAX_B 64

__device__ int g_inv[N_TOTAL];
__device__ int g_P;
__device__ int g_S;      // P + L : first right-pad index (taps >= S read as 0)
__device__ int g_ctr[MAX_B];

// Reset work counters, build inverse permutation, recover P. Cheap O(N).
__global__ void setup_kernel(const int* __restrict__ perm,
                             const int* __restrict__ off0,
                             const int* __restrict__ lout0,
                             int n_perm) {
    int j = threadIdx.x;
    if (j < MAX_B) g_ctr[j] = 0;
    if (j < n_perm) g_inv[perm[j]] = j;
    if (j == 0) {
        int d6  = off0[6] - off0[0];
        int pad = (lout0[0] - L_SEQ + d6) / 2;
        g_P = off0[0] + pad;
        g_S = g_P + L_SEQ;
    }
}

// Unchecked sliding-window conv (R5 proven core): s_m = bsv + sum_k wk[k]*p[(m+k)*d].
template<int KS>
__device__ __forceinline__ void conv_lane(
    const float* __restrict__ p, int steps, int d, float bsv,
    const float* __restrict__ wk, float& mx, int& cnt)
{
    if (steps <= 0) return;
    if (steps >= KS) {
        float y[KS];
#pragma unroll
        for (int j = 0; j < KS - 1; j++) y[j] = p[j * d];
        const float* pl = p + (KS - 1) * d;
        int i = 0;
        for (; i + KS <= steps; i += KS) {
#pragma unroll
            for (int u = 0; u < KS; u++) {
                y[(u + KS - 1) % KS] = *pl; pl += d;
                float s = bsv;
#pragma unroll
                for (int k = 0; k < KS; k++)
                    s = fmaf(wk[k], y[(u + k) % KS], s);
                mx = fmaxf(mx, s);
                cnt += (s > 0.0f);
            }
        }
        for (; i < steps; i++) {
            const float* q = p + i * d;
            float s = bsv;
#pragma unroll
            for (int k = 0; k < KS; k++) s = fmaf(wk[k], q[k * d], s);
            mx = fmaxf(mx, s);
            cnt += (s > 0.0f);
        }
    } else {
        for (int i = 0; i < steps; i++) {
            const float* q = p + i * d;
            float s = bsv;
#pragma unroll
            for (int k = 0; k < KS; k++) s = fmaf(wk[k], q[k * d], s);
            mx = fmaxf(mx, s);
            cnt += (s > 0.0f);
        }
    }
}

// Checked tail: taps with index >= S read as 0 (right zero-pad, not stored).
template<int KS>
__device__ __forceinline__ void conv_tail_checked(
    const float* __restrict__ sx, int base, int steps, int d, int S, float bsv,
    const float* __restrict__ wk, float& mx, int& cnt)
{
    for (int i = 0; i < steps; i++) {
        int j0 = base + i * d;
        float s = bsv;
#pragma unroll
        for (int k = 0; k < KS; k++) {
            int j = j0 + k * d;
            float v = (j < S) ? sx[j] : 0.0f;
            s = fmaf(wk[k], v, s);
        }
        mx = fmaxf(mx, s);
        cnt += (s > 0.0f);
    }
}

// Split a residue run at the point where the tap window would cross S,
// run the fast core on the safe prefix and the checked loop on the rest.
template<int KS>
__device__ __forceinline__ void conv_run(
    const float* __restrict__ sx, int abs0, int steps, int d, int S, float bsv,
    const float* __restrict__ wk, float& mx, int& cnt)
{
    if (steps <= 0) return;
    int lim = S - 1 - (KS - 1) * d - abs0;     // last abs tap0 with full window in-array
    int cut = (lim < 0) ? 0 : (lim / d + 1);
    if (cut > steps) cut = steps;
    conv_lane<KS>(sx + abs0, cut, d, bsv, wk, mx, cnt);
    conv_tail_checked<KS>(sx, abs0 + cut * d, steps - cut, d, S, bsv, wk, mx, cnt);
}

template<int KS>
__device__ __forceinline__ void run_group(
    const float* __restrict__ sx,          // [0,P)=zeros, [P,P+L)=x ; taps>=S are 0
    const float* __restrict__ w, const float* __restrict__ bias,
    const int*  __restrict__ off, const int* __restrict__ lout,
    float* __restrict__ out, int gi, int base, int b, int stride, int S)
{
    const int lane = threadIdx.x & 31;

    float wk[KS];
#pragma unroll
    for (int k = 0; k < KS; k++) wk[k] = __ldg(&w[gi * KS + k]);
    const int   o0  = __ldg(&off[gi * KS]);           // abs index of tap 0 at t=0
    const int   d   = __ldg(&off[gi * KS + 1]) - o0;  // dilation
    const float bsv = __ldg(&bias[gi]);
    const int   lo  = __ldg(&lout[gi]);

    float mx  = -FLT_MAX;
    int   cnt = 0;

    if (d < 32) {
        // lane -> (residue r, chunk g); uniform odd chunk size => conflict-free banks
        const int r = lane % d;
        const int g = lane / d;
        const int Mmax = (lo + d - 1) / d;
        const int Gmin = 32 / d;
        int mc = (Mmax + Gmin - 1) / Gmin;
        mc |= 1;                                   // round up to odd
        const int Mr = (r < lo) ? (lo - r + d - 1) / d : 0;
        int m0 = g * mc;
        int m1 = m0 + mc; if (m1 > Mr) m1 = Mr;
        if (m0 < m1)
            conv_run<KS>(sx, o0 + r + d * m0, m1 - m0, d, S, bsv, wk, mx, cnt);
    } else {
        // lanes = consecutive residues (consecutive addresses: conflict-free)
        for (int rb = 0; rb < d; rb += 32) {
            const int r = rb + lane;
            if (r < d) {
                const int Mr = (r < lo) ? (lo - r + d - 1) / d : 0;
                conv_run<KS>(sx, o0 + r, Mr, d, S, bsv, wk, mx, cnt);
            }
        }
    }

    // warp reductions
#pragma unroll
    for (int o = 16; o; o >>= 1) {
        mx   = fmaxf(mx, __shfl_xor_sync(0xffffffffu, mx, o));
        cnt += __shfl_xor_sync(0xffffffffu, cnt, o);
    }

    if (lane == 0) {
        int col = g_inv[base + gi];
        out[b * stride + 2 * col]     = mx;
        out[b * stride + 2 * col + 1] = (float)cnt / (float)lo;
    }
}

__global__ __launch_bounds__(TPB, 5)
void rocket_all_kernel(
    const float* __restrict__ x,
    const float* __restrict__ w0, const float* __restrict__ b0,
    const int*  __restrict__ off0, const int* __restrict__ lout0, int n0,
    const float* __restrict__ w1, const float* __restrict__ b1,
    const int*  __restrict__ off1, const int* __restrict__ lout1, int n1,
    const float* __restrict__ w2, const float* __restrict__ b2,
    const int*  __restrict__ off2, const int* __restrict__ lout2, int n2,
    float* __restrict__ out, int stride)
{
    __shared__ float sx[SX_WORDS];
    const int b = blockIdx.y;
    const int P = g_P;
    const int S = g_S;
    const int N = n0 + n1 + n2;

    // zero left pad [0,P)
    for (int i = threadIdx.x; i < P; i += TPB)
        sx[i] = 0.0f;
    // stage x[b] into sx[P .. P+L): P even => float2-aligned
    {
        const float2* xb2 = (const float2*)(x + (size_t)b * L_SEQ);
        float2* dst = (float2*)(sx + P);
        for (int i = threadIdx.x; i < L_SEQ / 2; i += TPB)
            dst[i] = xb2[i];
    }
    __syncthreads();

    const int lane = threadIdx.x & 31;

    // warp-granular work stealing over kernels for this batch
    for (;;) {
        int item = 0;
        if (lane == 0) item = atomicAdd(&g_ctr[b], 1);
        item = __shfl_sync(0xffffffffu, item, 0);
        if (item >= N) break;

        if (item < n0) {
            run_group<7>(sx, w0, b0, off0, lout0, out, item, 0, b, stride, S);
        } else if (item < n0 + n1) {
            run_group<9>(sx, w1, b1, off1, lout1, out, item - n0, n0, b, stride, S);
        } else {
            run_group<11>(sx, w2, b2, off2, lout2, out, item - n0 - n1, n0 + n1, b, stride, S);
        }
    }
}

extern "C" void kernel_launch(void* const* d_in, const int* in_sizes, int n_in,
                              void* d_out, int out_size) {
    // Dict order:      x, perm, P, w0,b0,off0,lout0, w1,b1,off1,lout1, w2,b2,off2,lout2
    // Signature order: x, w0,b0,off0,lout0, w1,b1,off1,lout1, w2,b2,off2,lout2, perm, P
    int ix, iperm, ig0, ig1, ig2;
    if (n_in >= 3 && in_sizes[1] == N_TOTAL && in_sizes[2] == 1) {
        ix = 0; iperm = 1; ig0 = 3; ig1 = 7; ig2 = 11;
    } else {
        ix = 0; ig0 = 1; ig1 = 5; ig2 = 9; iperm = 13;
    }

    const float* x     = (const float*)d_in[ix];
    const int*   perm  = (const int*)  d_in[iperm];

    const float* w0    = (const float*)d_in[ig0 + 0];
    const float* b0    = (const float*)d_in[ig0 + 1];
    const int*   off0  = (const int*)  d_in[ig0 + 2];
    const int*   lout0 = (const int*)  d_in[ig0 + 3];
    const float* w1    = (const float*)d_in[ig1 + 0];
    const float* b1    = (const float*)d_in[ig1 + 1];
    const int*   off1  = (const int*)  d_in[ig1 + 2];
    const int*   lout1 = (const int*)  d_in[ig1 + 3];
    const float* w2    = (const float*)d_in[ig2 + 0];
    const float* b2    = (const float*)d_in[ig2 + 1];
    const int*   off2  = (const int*)  d_in[ig2 + 2];
    const int*   lout2 = (const int*)  d_in[ig2 + 3];

    const int n0 = in_sizes[ig0 + 1];
    const int n1 = in_sizes[ig1 + 1];
    const int n2 = in_sizes[ig2 + 1];
    const int B  = in_sizes[ix] / L_SEQ;
    const int N  = n0 + n1 + n2;
    const int stride = 2 * N;

    setup_kernel<<<1, N_TOTAL>>>(perm, off0, lout0, in_sizes[iperm]);

    // persistent balanced grid: ~5 blocks/SM * 148 SMs = 740 blocks
    int bpb = 740 / (B > 0 ? B : 1);
    if (bpb < 1) bpb = 1;
    int max_bpb = (N + WPB - 1) / WPB;
    if (bpb > max_bpb) bpb = max_bpb;

    dim3 grid(bpb, B);
    rocket_all_kernel<<<grid, TPB>>>(
        x,
        w0, b0, off0, lout0, n0,
        w1, b1, off1, lout1, n1,
        w2, b2, off2, lout2, n2,
        (float*)d_out, stride);
}

// round 14
// speedup vs baseline: 1.3639x; 1.3639x over previous
#include <cuda_runtime.h>
#include <float.h>

#define L_SEQ 4096
#define N_TOTAL 512
#define WPB 8            // warps per block
#define TPB (WPB * 32)
#define PAD_MAX 4096     // P <= 4094
#define LP_MAX (L_SEQ + 2 * PAD_MAX)   // 12288 floats = 48KB static shared
#define MAX_B 64

__device__ int g_inv[N_TOTAL];
__device__ int g_P;
__device__ int g_ctr[MAX_B];

// Reset work counters, build inverse permutation, recover P. Cheap O(N).
__global__ void setup_kernel(const int* __restrict__ perm,
                             const int* __restrict__ off0,
                             const int* __restrict__ lout0,
                             int n_perm) {
    int j = threadIdx.x;
    if (j < MAX_B) g_ctr[j] = 0;
    if (j < n_perm) g_inv[perm[j]] = j;
    if (j == 0) {
        int d6  = off0[6] - off0[0];
        int pad = (lout0[0] - L_SEQ + d6) / 2;
        g_P = off0[0] + pad;
    }
}

// Unchecked sliding-window conv (R5 proven core): s_m = bsv + sum_k wk[k]*p[(m+k)*d].
template<int KS>
__device__ __forceinline__ void conv_lane(
    const float* __restrict__ p, int steps, int d, float bsv,
    const float* __restrict__ wk, float& mx, int& cnt)
{
    if (steps <= 0) return;
    if (steps >= KS) {
        float y[KS];
#pragma unroll
        for (int j = 0; j < KS - 1; j++) y[j] = p[j * d];
        const float* pl = p + (KS - 1) * d;
        int i = 0;
        for (; i + KS <= steps; i += KS) {
#pragma unroll
            for (int u = 0; u < KS; u++) {
                y[(u + KS - 1) % KS] = *pl; pl += d;
                float s = bsv;
#pragma unroll
                for (int k = 0; k < KS; k++)
                    s = fmaf(wk[k], y[(u + k) % KS], s);
                mx = fmaxf(mx, s);
                cnt += (s > 0.0f);
            }
        }
        for (; i < steps; i++) {
            const float* q = p + i * d;
            float s = bsv;
#pragma unroll
            for (int k = 0; k < KS; k++) s = fmaf(wk[k], q[k * d], s);
            mx = fmaxf(mx, s);
            cnt += (s > 0.0f);
        }
    } else {
        for (int i = 0; i < steps; i++) {
            const float* q = p + i * d;
            float s = bsv;
#pragma unroll
            for (int k = 0; k < KS; k++) s = fmaf(wk[k], q[k * d], s);
            mx = fmaxf(mx, s);
            cnt += (s > 0.0f);
        }
    }
}

template<int KS>
__device__ __forceinline__ void run_group(
    const float* __restrict__ sx,          // zero-padded: x lives at [P, P+L)
    const float* __restrict__ w, const float* __restrict__ bias,
    const int*  __restrict__ off, const int* __restrict__ lout,
    float* __restrict__ out, int gi, int base, int b, int stride)
{
    const int lane = threadIdx.x & 31;

    float wk[KS];
#pragma unroll
    for (int k = 0; k < KS; k++) wk[k] = __ldg(&w[gi * KS + k]);
    const int   o0  = __ldg(&off[gi * KS]);           // padded-array base for tap 0
    const int   d   = __ldg(&off[gi * KS + 1]) - o0;  // dilation
    const float bsv = __ldg(&bias[gi]);
    const int   lo  = __ldg(&lout[gi]);

    float mx  = -FLT_MAX;
    int   cnt = 0;
    const float* px = sx + o0;

    // Uniform virtual-slot partition: outputs t = r + d*m enumerated as
    // slots s in [0, d*M), s -> (r = s/M, m = s%M), M = ceil(lo/d).
    // Each lane takes a contiguous chunk of ceil(d*M/32) slots: every lane
    // gets ~lo/32 outputs for EVERY d; no idle lanes, one code path.
    const int M = (lo + d - 1) / d;
    const int total = d * M;
    const int cs = (total + 31) >> 5;
    int s0 = lane * cs;
    int s1 = s0 + cs; if (s1 > total) s1 = total;

    while (s0 < s1) {
        int r = s0 / M;
        int m = s0 - r * M;
        int run = s1 - s0;                     // slots left for this lane
        int inres = M - m;                     // slots left in residue r
        if (run > inres) run = inres;
        // actual valid outputs for residue r: Mr = ceil((lo - r)/d) for r < lo
        int Mr = (r < lo) ? (lo - r + d - 1) / d : 0;
        int real = Mr - m; if (real > run) real = run;
        if (real > 0)
            conv_lane<KS>(px + r + d * m, real, d, bsv, wk, mx, cnt);
        s0 += run;
    }

    // warp reductions
#pragma unroll
    for (int o = 16; o; o >>= 1) {
        mx   = fmaxf(mx, __shfl_xor_sync(0xffffffffu, mx, o));
        cnt += __shfl_xor_sync(0xffffffffu, cnt, o);
    }

    if (lane == 0) {
        int col = g_inv[base + gi];
        out[b * stride + 2 * col]     = mx;
        out[b * stride + 2 * col + 1] = (float)cnt / (float)lo;
    }
}

__global__ __launch_bounds__(TPB)
void rocket_all_kernel(
    const float* __restrict__ x,
    const float* __restrict__ w0, const float* __restrict__ b0,
    const int*  __restrict__ off0, const int* __restrict__ lout0, int n0,
    const float* __restrict__ w1, const float* __restrict__ b1,
    const int*  __restrict__ off1, const int* __restrict__ lout1, int n1,
    const float* __restrict__ w2, const float* __restrict__ b2,
    const int*  __restrict__ off2, const int* __restrict__ lout2, int n2,
    float* __restrict__ out, int stride)
{
    __shared__ float sx[LP_MAX];
    const int b = blockIdx.y;
    const int P = g_P;
    const int N = n0 + n1 + n2;

    // zero pad regions [0,P) and [P+L, P+L+P)
    for (int i = threadIdx.x; i < P; i += TPB) {
        sx[i]             = 0.0f;
        sx[P + L_SEQ + i] = 0.0f;
    }
    // stage x[b] into sx[P .. P+L): P even => float2-aligned
    {
        const float2* xb2 = (const float2*)(x + (size_t)b * L_SEQ);
        float2* dst = (float2*)(sx + P);
        for (int i = threadIdx.x; i < L_SEQ / 2; i += TPB)
            dst[i] = xb2[i];
    }
    __syncthreads();

    const int lane = threadIdx.x & 31;

    // warp-granular work stealing over kernels for this batch
    for (;;) {
        int item = 0;
        if (lane == 0) item = atomicAdd(&g_ctr[b], 1);
        item = __shfl_sync(0xffffffffu, item, 0);
        if (item >= N) break;

        if (item < n0) {
            run_group<7>(sx, w0, b0, off0, lout0, out, item, 0, b, stride);
        } else if (item < n0 + n1) {
            run_group<9>(sx, w1, b1, off1, lout1, out, item - n0, n0, b, stride);
        } else {
            run_group<11>(sx, w2, b2, off2, lout2, out, item - n0 - n1, n0 + n1, b, stride);
        }
    }
}

extern "C" void kernel_launch(void* const* d_in, const int* in_sizes, int n_in,
                              void* d_out, int out_size) {
    // Dict order:      x, perm, P, w0,b0,off0,lout0, w1,b1,off1,lout1, w2,b2,off2,lout2
    // Signature order: x, w0,b0,off0,lout0, w1,b1,off1,lout1, w2,b2,off2,lout2, perm, P
    int ix, iperm, ig0, ig1, ig2;
    if (n_in >= 3 && in_sizes[1] == N_TOTAL && in_sizes[2] == 1) {
        ix = 0; iperm = 1; ig0 = 3; ig1 = 7; ig2 = 11;
    } else {
        ix = 0; ig0 = 1; ig1 = 5; ig2 = 9; iperm = 13;
    }

    const float* x     = (const float*)d_in[ix];
    const int*   perm  = (const int*)  d_in[iperm];

    const float* w0    = (const float*)d_in[ig0 + 0];
    const float* b0    = (const float*)d_in[ig0 + 1];
    const int*   off0  = (const int*)  d_in[ig0 + 2];
    const int*   lout0 = (const int*)  d_in[ig0 + 3];
    const float* w1    = (const float*)d_in[ig1 + 0];
    const float* b1    = (const float*)d_in[ig1 + 1];
    const int*   off1  = (const int*)  d_in[ig1 + 2];
    const int*   lout1 = (const int*)  d_in[ig1 + 3];
    const float* w2    = (const float*)d_in[ig2 + 0];
    const float* b2    = (const float*)d_in[ig2 + 1];
    const int*   off2  = (const int*)  d_in[ig2 + 2];
    const int*   lout2 = (const int*)  d_in[ig2 + 3];

    const int n0 = in_sizes[ig0 + 1];
    const int n1 = in_sizes[ig1 + 1];
    const int n2 = in_sizes[ig2 + 1];
    const int B  = in_sizes[ix] / L_SEQ;
    const int N  = n0 + n1 + n2;
    const int stride = 2 * N;

    setup_kernel<<<1, N_TOTAL>>>(perm, off0, lout0, in_sizes[iperm]);

    // persistent balanced grid: ~4 blocks/SM * 148 SMs
    int bpb = 592 / (B > 0 ? B : 1);
    if (bpb < 1) bpb = 1;
    int max_bpb = (N + WPB - 1) / WPB;
    if (bpb > max_bpb) bpb = max_bpb;

    dim3 grid(bpb, B);
    rocket_all_kernel<<<grid, TPB>>>(
        x,
        w0, b0, off0, lout0, n0,
        w1, b1, off1, lout1, n1,
        w2, b2, off2, lout2, n2,
        (float*)d_out, stride);
}

// round 15
// speedup vs baseline: 1.4424x; 1.0576x over previous
#include <cuda_runtime.h>
#include <float.h>

#define L_SEQ 4096
#define N_TOTAL 512
#define WPB 8            // warps per block
#define TPB (WPB * 32)
#define PAD_MAX 4096     // P <= 4094
#define LP_MAX (L_SEQ + 2 * PAD_MAX)   // 12288 floats = 48KB static shared
#define MAX_B 64

__device__ int g_inv[N_TOTAL];
__device__ int g_P;
__device__ int g_ctr[MAX_B];

// Reset work counters, build inverse permutation, recover P. Cheap O(N).
__global__ void setup_kernel(const int* __restrict__ perm,
                             const int* __restrict__ off0,
                             const int* __restrict__ lout0,
                             int n_perm) {
    int j = threadIdx.x;
    if (j < MAX_B) g_ctr[j] = 0;
    if (j < n_perm) g_inv[perm[j]] = j;
    if (j == 0) {
        int d6  = off0[6] - off0[0];
        int pad = (lout0[0] - L_SEQ + d6) / 2;
        g_P = off0[0] + pad;
    }
}

// Sliding-window conv (R5 core) with dual reduction accumulators:
// even outputs fold into (mxa, ca), odd into (mxb, cb) -> halves the
// loop-carried FMNMX/IADD recurrence without touching the FMA chains.
template<int KS>
__device__ __forceinline__ void conv_lane(
    const float* __restrict__ p, int steps, int d, float bsv,
    const float* __restrict__ wk,
    float& mxa, float& mxb, int& ca, int& cb)
{
    if (steps <= 0) return;
    if (steps >= KS) {
        float y[KS];
#pragma unroll
        for (int j = 0; j < KS - 1; j++) y[j] = p[j * d];
        const float* pl = p + (KS - 1) * d;
        int i = 0;
        for (; i + KS <= steps; i += KS) {
#pragma unroll
            for (int u = 0; u < KS; u++) {
                y[(u + KS - 1) % KS] = *pl; pl += d;
                float s = bsv;
#pragma unroll
                for (int k = 0; k < KS; k++)
                    s = fmaf(wk[k], y[(u + k) % KS], s);
                if (u & 1) { mxb = fmaxf(mxb, s); cb += (s > 0.0f); }
                else       { mxa = fmaxf(mxa, s); ca += (s > 0.0f); }
            }
        }
        for (; i < steps; i++) {
            const float* q = p + i * d;
            float s = bsv;
#pragma unroll
            for (int k = 0; k < KS; k++) s = fmaf(wk[k], q[k * d], s);
            mxa = fmaxf(mxa, s);
            ca += (s > 0.0f);
        }
    } else {
        for (int i = 0; i < steps; i++) {
            const float* q = p + i * d;
            float s = bsv;
#pragma unroll
            for (int k = 0; k < KS; k++) s = fmaf(wk[k], q[k * d], s);
            mxa = fmaxf(mxa, s);
            ca += (s > 0.0f);
        }
    }
}

template<int KS>
__device__ __forceinline__ void run_group(
    const float* __restrict__ sx,          // zero-padded: x lives at [P, P+L)
    const float* __restrict__ w, const float* __restrict__ bias,
    const int*  __restrict__ off, const int* __restrict__ lout,
    float* __restrict__ out, int gi, int base, int b, int stride)
{
    const int lane = threadIdx.x & 31;

    float wk[KS];
#pragma unroll
    for (int k = 0; k < KS; k++) wk[k] = __ldg(&w[gi * KS + k]);
    const int   o0  = __ldg(&off[gi * KS]);           // padded-array base for tap 0
    const int   d   = __ldg(&off[gi * KS + 1]) - o0;  // dilation
    const float bsv = __ldg(&bias[gi]);
    const int   lo  = __ldg(&lout[gi]);

    float mxa = -FLT_MAX, mxb = -FLT_MAX;
    int   ca = 0, cb = 0;
    const float* px = sx + o0;

    if (d < 32) {
        // lane -> (residue r, chunk g); uniform odd chunk size => conflict-free banks
        const int r = lane % d;
        const int g = lane / d;
        const int Mmax = (lo + d - 1) / d;
        const int Gmin = 32 / d;
        int mc = (Mmax + Gmin - 1) / Gmin;
        mc |= 1;                                   // round up to odd
        const int Mr = (r < lo) ? (lo - r + d - 1) / d : 0;
        int m0 = g * mc;
        int m1 = m0 + mc; if (m1 > Mr) m1 = Mr;
        if (m0 < m1)
            conv_lane<KS>(px + r + d * m0, m1 - m0, d, bsv, wk, mxa, mxb, ca, cb);
    } else {
        // lanes = consecutive residues (consecutive addresses: conflict-free)
        for (int rb = 0; rb < d; rb += 32) {
            const int r = rb + lane;
            if (r < d) {
                const int Mr = (r < lo) ? (lo - r + d - 1) / d : 0;
                conv_lane<KS>(px + r, Mr, d, bsv, wk, mxa, mxb, ca, cb);
            }
        }
    }

    float mx  = fmaxf(mxa, mxb);
    int   cnt = ca + cb;

    // warp reductions
#pragma unroll
    for (int o = 16; o; o >>= 1) {
        mx   = fmaxf(mx, __shfl_xor_sync(0xffffffffu, mx, o));
        cnt += __shfl_xor_sync(0xffffffffu, cnt, o);
    }

    if (lane == 0) {
        int col = g_inv[base + gi];
        out[b * stride + 2 * col]     = mx;
        out[b * stride + 2 * col + 1] = (float)cnt / (float)lo;
    }
}

__global__ __launch_bounds__(TPB)
void rocket_all_kernel(
    const float* __restrict__ x,
    const float* __restrict__ w0, const float* __restrict__ b0,
    const int*  __restrict__ off0, const int* __restrict__ lout0, int n0,
    const float* __restrict__ w1, const float* __restrict__ b1,
    const int*  __restrict__ off1, const int* __restrict__ lout1, int n1,
    const float* __restrict__ w2, const float* __restrict__ b2,
    const int*  __restrict__ off2, const int* __restrict__ lout2, int n2,
    float* __restrict__ out, int stride)
{
    __shared__ float sx[LP_MAX];
    const int b = blockIdx.y;
    const int P = g_P;
    const int N = n0 + n1 + n2;

    // zero pad regions [0,P) and [P+L, P+L+P)
    for (int i = threadIdx.x; i < P; i += TPB) {
        sx[i]             = 0.0f;
        sx[P + L_SEQ + i] = 0.0f;
    }
    // stage x[b] into sx[P .. P+L): P even => float2-aligned
    {
        const float2* xb2 = (const float2*)(x + (size_t)b * L_SEQ);
        float2* dst = (float2*)(sx + P);
        for (int i = threadIdx.x; i < L_SEQ / 2; i += TPB)
            dst[i] = xb2[i];
    }
    __syncthreads();

    const int lane = threadIdx.x & 31;

    // work stealing with one-item prefetch: the atomicAdd for the NEXT item
    // is issued before computing the current one, hiding ~320 cyc L2-atomic
    // latency behind the item's compute.
    int next = 0;
    if (lane == 0) next = atomicAdd(&g_ctr[b], 1);
    next = __shfl_sync(0xffffffffu, next, 0);

    while (next < N) {
        const int item = next;
        if (lane == 0) next = atomicAdd(&g_ctr[b], 1);   // prefetch next item
        next = __shfl_sync(0xffffffffu, next, 0);

        if (item < n0) {
            run_group<7>(sx, w0, b0, off0, lout0, out, item, 0, b, stride);
        } else if (item < n0 + n1) {
            run_group<9>(sx, w1, b1, off1, lout1, out, item - n0, n0, b, stride);
        } else {
            run_group<11>(sx, w2, b2, off2, lout2, out, item - n0 - n1, n0 + n1, b, stride);
        }
    }
}

extern "C" void kernel_launch(void* const* d_in, const int* in_sizes, int n_in,
                              void* d_out, int out_size) {
    // Dict order:      x, perm, P, w0,b0,off0,lout0, w1,b1,off1,lout1, w2,b2,off2,lout2
    // Signature order: x, w0,b0,off0,lout0, w1,b1,off1,lout1, w2,b2,off2,lout2, perm, P
    int ix, iperm, ig0, ig1, ig2;
    if (n_in >= 3 && in_sizes[1] == N_TOTAL && in_sizes[2] == 1) {
        ix = 0; iperm = 1; ig0 = 3; ig1 = 7; ig2 = 11;
    } else {
        ix = 0; ig0 = 1; ig1 = 5; ig2 = 9; iperm = 13;
    }

    const float* x     = (const float*)d_in[ix];
    const int*   perm  = (const int*)  d_in[iperm];

    const float* w0    = (const float*)d_in[ig0 + 0];
    const float* b0    = (const float*)d_in[ig0 + 1];
    const int*   off0  = (const int*)  d_in[ig0 + 2];
    const int*   lout0 = (const int*)  d_in[ig0 + 3];
    const float* w1    = (const float*)d_in[ig1 + 0];
    const float* b1    = (const float*)d_in[ig1 + 1];
    const int*   off1  = (const int*)  d_in[ig1 + 2];
    const int*   lout1 = (const int*)  d_in[ig1 + 3];
    const float* w2    = (const float*)d_in[ig2 + 0];
    const float* b2    = (const float*)d_in[ig2 + 1];
    const int*   off2  = (const int*)  d_in[ig2 + 2];
    const int*   lout2 = (const int*)  d_in[ig2 + 3];

    const int n0 = in_sizes[ig0 + 1];
    const int n1 = in_sizes[ig1 + 1];
    const int n2 = in_sizes[ig2 + 1];
    const int B  = in_sizes[ix] / L_SEQ;
    const int N  = n0 + n1 + n2;
    const int stride = 2 * N;

    setup_kernel<<<1, N_TOTAL>>>(perm, off0, lout0, in_sizes[iperm]);

    // persistent balanced grid: ~4 blocks/SM * 148 SMs
    int bpb = 592 / (B > 0 ? B : 1);
    if (bpb < 1) bpb = 1;
    int max_bpb = (N + WPB - 1) / WPB;
    if (bpb > max_bpb) bpb = max_bpb;

    dim3 grid(bpb, B);
    rocket_all_kernel<<<grid, TPB>>>(
        x,
        w0, b0, off0, lout0, n0,
        w1, b1, off1, lout1, n1,
        w2, b2, off2, lout2, n2,
        (float*)d_out, stride);
}